// round 14
// baseline (speedup 1.0000x reference)
#include <cuda_runtime.h>
#include <math_constants.h>
#include <stdint.h>

#define B_    2
#define C_    128
#define N_    4096
#define GR_   32
#define CPG_  4
#define NH_   4
#define HD_   32
#define TK_   256
#define EPS_  1e-5f
#define SCALE_ 0.17677669529663689f   // 32^-0.5
#define CANDMAX_ 1024
#define EXTMAX_  64

typedef unsigned long long ull;

// -------- scratch (device globals; no allocation allowed) --------
static __device__ float g_h[B_*C_*N_];
static __device__ float g_q[B_*NH_*N_*HD_];
static __device__ float g_k[B_*NH_*N_*HD_];
static __device__ float g_v[B_*NH_*N_*HD_];
static __device__ float g_att[B_*C_*N_];
static __device__ float g_scores[(size_t)B_*NH_*N_*N_];  // 512 MB

__device__ __forceinline__ unsigned ordf(float f) {
    unsigned u = __float_as_uint(f);
    return (u & 0x80000000u) ? ~u : (u | 0x80000000u);
}
__device__ __forceinline__ float iordf(unsigned u) {
    return __uint_as_float((u & 0x80000000u) ? (u ^ 0x80000000u) : ~u);
}

// ---- packed fp32x2 helpers (SASS FFMA2: PTX-only, bit-identical to 2x FFMA) ----
__device__ __forceinline__ ull pack2(float lo, float hi) {
    ull r; asm("mov.b64 %0, {%1, %2};" : "=l"(r) : "f"(lo), "f"(hi)); return r;
}
__device__ __forceinline__ void unpack2(float& lo, float& hi, ull v) {
    asm("mov.b64 {%0, %1}, %2;" : "=f"(lo), "=f"(hi) : "l"(v));
}
__device__ __forceinline__ void fma2(ull& d, ull a, ull b) {
    asm("fma.rn.f32x2 %0, %1, %2, %3;" : "=l"(d) : "l"(a), "l"(b), "l"(d));
}

// ================= GroupNorm =================
__global__ void __launch_bounds__(256) gn_kernel(const float* __restrict__ x,
                                                 const float* __restrict__ w,
                                                 const float* __restrict__ b) {
    int bg = blockIdx.x;
    int bb = bg / GR_, g = bg % GR_;
    const float* xp = x + ((size_t)bb*C_ + g*CPG_) * N_;
    float*       hp = g_h + ((size_t)bb*C_ + g*CPG_) * N_;
    int tid = threadIdx.x;

    float s = 0.f, s2 = 0.f;
    for (int i = tid; i < CPG_*N_; i += 256) {
        float v = xp[i];
        s += v; s2 += v*v;
    }
    __shared__ float rs[8], rs2[8];
    __shared__ float mu_s, rstd_s;
    #pragma unroll
    for (int o = 16; o; o >>= 1) {
        s  += __shfl_down_sync(0xffffffffu, s,  o);
        s2 += __shfl_down_sync(0xffffffffu, s2, o);
    }
    if ((tid & 31) == 0) { rs[tid>>5] = s; rs2[tid>>5] = s2; }
    __syncthreads();
    if (tid == 0) {
        float t = 0.f, t2 = 0.f;
        #pragma unroll
        for (int i = 0; i < 8; i++) { t += rs[i]; t2 += rs2[i]; }
        float inv = 1.f / (float)(CPG_*N_);
        float mu = t * inv;
        float var = t2 * inv - mu*mu;
        mu_s = mu;
        rstd_s = rsqrtf(var + EPS_);
    }
    __syncthreads();
    float mu = mu_s, rstd = rstd_s;
    for (int i = tid; i < CPG_*N_; i += 256) {
        int c = g*CPG_ + i / N_;
        hp[i] = (xp[i] - mu) * rstd * w[c] + b[c];
    }
}

// ================= QKV GEMM =================
__global__ void __launch_bounds__(256) qkv_kernel(const float* __restrict__ W,
                                                  const float* __restrict__ bias) {
    __shared__ float hs[C_*64];
    int n0 = blockIdx.x * 64;
    int bb = blockIdx.y;
    int tid = threadIdx.x;
    const float* hp = g_h + (size_t)bb * C_ * N_;
    for (int i = tid; i < C_*64; i += 256) {
        int c = i >> 6, nl = i & 63;
        hs[i] = hp[(size_t)c*N_ + n0 + nl];
    }
    __syncthreads();

    int nq = tid & 3;
    int og = tid >> 2;
    float acc[6][16];
    #pragma unroll
    for (int k = 0; k < 6; k++)
        #pragma unroll
        for (int j = 0; j < 16; j++) acc[k][j] = 0.f;

    const float4* hs4 = (const float4*)hs;
    for (int c = 0; c < C_; c++) {
        float4 h0 = hs4[c*16 + nq*4 + 0];
        float4 h1 = hs4[c*16 + nq*4 + 1];
        float4 h2 = hs4[c*16 + nq*4 + 2];
        float4 h3 = hs4[c*16 + nq*4 + 3];
        float hv[16] = {h0.x,h0.y,h0.z,h0.w, h1.x,h1.y,h1.z,h1.w,
                        h2.x,h2.y,h2.z,h2.w, h3.x,h3.y,h3.z,h3.w};
        #pragma unroll
        for (int k = 0; k < 6; k++) {
            float wv = W[(size_t)(og + 64*k)*C_ + c];
            #pragma unroll
            for (int j = 0; j < 16; j++) acc[k][j] += wv * hv[j];
        }
    }
    #pragma unroll
    for (int k = 0; k < 6; k++) {
        int o = og + 64*k;
        int which = o >> 7, r = o & 127;
        int head = r >> 5, d = r & 31;
        float* dst = (which == 0) ? g_q : ((which == 1) ? g_k : g_v);
        dst += ((size_t)(bb*NH_ + head) * N_) * HD_ + d;
        float bv = bias[o];
        #pragma unroll
        for (int j = 0; j < 16; j++)
            dst[(size_t)(n0 + nq*16 + j) * HD_] = acc[k][j] + bv;
    }
}

// ================= scores = scale * Q K^T (packed f32x2 FMA) =================
__global__ void __launch_bounds__(256) score_kernel() {
    __shared__ float qs[HD_*128];
    __shared__ float ks[HD_*128];
    int bh = blockIdx.z;
    int i0 = blockIdx.y * 128, j0 = blockIdx.x * 128;
    const float* qp = g_q + (size_t)bh * N_ * HD_;
    const float* kp = g_k + (size_t)bh * N_ * HD_;
    int tid = threadIdx.x;

    for (int i = tid; i < 1024; i += 256) {
        int row = i >> 3, d4 = i & 7;
        float4 a = *(const float4*)&qp[(size_t)(i0 + row)*HD_ + d4*4];
        float4 b = *(const float4*)&kp[(size_t)(j0 + row)*HD_ + d4*4];
        int c0 = d4 * 4;
        qs[(c0+0)*128 + row] = a.x; qs[(c0+1)*128 + row] = a.y;
        qs[(c0+2)*128 + row] = a.z; qs[(c0+3)*128 + row] = a.w;
        ks[(c0+0)*128 + row] = b.x; ks[(c0+1)*128 + row] = b.y;
        ks[(c0+2)*128 + row] = b.z; ks[(c0+3)*128 + row] = b.w;
    }
    __syncthreads();

    int tx = tid & 15, ty = tid >> 4;
    const float4* qs4 = (const float4*)qs;
    const float4* ks4 = (const float4*)ks;
    ull acc2[8][4];
    #pragma unroll
    for (int r = 0; r < 8; r++)
        #pragma unroll
        for (int c = 0; c < 4; c++) acc2[r][c] = 0ull;

    #pragma unroll
    for (int kk = 0; kk < HD_; kk++) {
        float4 aL = qs4[kk*32 + ty];
        float4 aH = qs4[kk*32 + 16 + ty];
        float4 bL = ks4[kk*32 + tx];
        float4 bH = ks4[kk*32 + 16 + tx];
        ull av2[8] = {pack2(aL.x,aL.x), pack2(aL.y,aL.y), pack2(aL.z,aL.z), pack2(aL.w,aL.w),
                      pack2(aH.x,aH.x), pack2(aH.y,aH.y), pack2(aH.z,aH.z), pack2(aH.w,aH.w)};
        ull bv2[4] = {pack2(bL.x,bL.y), pack2(bL.z,bL.w),
                      pack2(bH.x,bH.y), pack2(bH.z,bH.w)};
        #pragma unroll
        for (int r = 0; r < 8; r++)
            #pragma unroll
            for (int c = 0; c < 4; c++)
                fma2(acc2[r][c], av2[r], bv2[c]);
    }

    float* sp = g_scores + (size_t)bh * N_ * N_;
    #pragma unroll
    for (int r = 0; r < 8; r++) {
        int i = i0 + ((r < 4) ? (ty*4 + r) : (64 + ty*4 + (r - 4)));
        #pragma unroll
        for (int half = 0; half < 2; half++) {
            int j = j0 + half*64 + tx*4;
            float e0, e1, e2, e3;
            unpack2(e0, e1, acc2[r][half*2 + 0]);
            unpack2(e2, e3, acc2[r][half*2 + 1]);
            float4 o;
            o.x = e0 * SCALE_;
            o.y = e1 * SCALE_;
            o.z = e2 * SCALE_;
            o.w = e3 * SCALE_;
            __stcs((float4*)&sp[(size_t)i*N_ + j], o);
        }
    }
}

// ---- block count of (u[k] >= t) over all 4096 register-resident values ----
__device__ __forceinline__ int block_count_ge(const unsigned* u, unsigned t,
                                              volatile unsigned* warru,
                                              int lane, int w) {
    int cnt = 0;
    #pragma unroll
    for (int k = 0; k < 16; k++) cnt += (u[k] >= t) ? 1 : 0;
    cnt = __reduce_add_sync(0xffffffffu, (unsigned)cnt);
    __syncthreads();
    if (lane == 0) warru[w] = (unsigned)cnt;
    __syncthreads();
    int c = 0;
    #pragma unroll
    for (int q = 0; q < 8; q++) c += (int)warru[q];
    return c;
}

// ---- block scan of per-thread candidate count; returns total, sets pos ----
__device__ __forceinline__ int scan_count(const unsigned* u, unsigned t,
                                          volatile unsigned* wtt,
                                          int lane, int w, int* pos_out) {
    int cnt = 0;
    #pragma unroll
    for (int k = 0; k < 16; k++) cnt += (u[k] >= t) ? 1 : 0;
    int inc = cnt;
    #pragma unroll
    for (int off = 1; off < 32; off <<= 1) {
        int v = __shfl_up_sync(0xffffffffu, inc, off);
        if (lane >= off) inc += v;
    }
    __syncthreads();                       // wtt reuse from prior round
    if (lane == 31) wtt[w] = (unsigned)inc;
    __syncthreads();
    int wbase = 0, tot = 0;
    #pragma unroll
    for (int q = 0; q < 8; q++) {
        int v = (int)wtt[q];
        tot += v;
        if (q < w) wbase += v;
    }
    *pos_out = wbase + inc - cnt;          // exclusive offset for this thread
    return tot;
}

// ---- 256-bin suffix selection; writes ctrl[0]=bin, ctrl[2]=kth', ctrl[3]=bincnt ----
__device__ __forceinline__ void bin_select8(unsigned* hist, unsigned* wtt,
                                            unsigned* ctrl, int tid, int lane,
                                            int w, int kth) {
    unsigned c = hist[tid];
    unsigned s = c;
    #pragma unroll
    for (int off = 1; off < 32; off <<= 1) {
        unsigned o = __shfl_down_sync(0xffffffffu, s, off);
        if (lane + off < 32) s += o;
    }
    if (lane == 0) wtt[w] = s;
    __syncthreads();
    unsigned add = 0;
    #pragma unroll
    for (int q = 0; q < 8; q++) if (q > w) add += wtt[q];
    unsigned Sincl = s + add;
    unsigned Sexcl = Sincl - c;
    if (Sexcl < (unsigned)kth && (unsigned)kth <= Sincl) {
        ctrl[0] = (unsigned)tid;
        ctrl[2] = (unsigned)kth - Sexcl;
        ctrl[3] = c;
    }
    __syncthreads();
}

// ================= top-256 select + softmax AV =====================
// 44-bit keys (u<<12)|(4095-idx) == lax.top_k semantics. Stat threshold ->
// scan-compacted candidates -> radix with early-exit brute rank.
__global__ void __launch_bounds__(256) select_kernel() {
    __shared__ ull      cand[CANDMAX_];   // 8 KB candidate keys
    __shared__ ull      cext[EXTMAX_];
    __shared__ ull      skey;
    __shared__ ull      selkw[TK_];       // 2 KB packed (wt,idx)
    __shared__ unsigned hist[256];        // 1 KB
    __shared__ float    warrf[3*8];
    __shared__ unsigned wtt[8];
    __shared__ unsigned ctrl[8];
    __shared__ unsigned scnt[4];
    __shared__ int      eqidx[256];
    __shared__ __align__(16) float racc[8*HD_];

    int n = blockIdx.x, bh = blockIdx.y;
    const float4* sp4 = (const float4*)(g_scores + (size_t)bh*N_*N_ + (size_t)n*N_);
    const float* vp = g_v + (size_t)bh*N_*HD_;
    int tid = threadIdx.x;
    int lane = tid & 31, w = tid >> 5;

    if (tid < 4) scnt[tid] = 0;

    // ---- load row into registers (ordf) + sum/sum2/max ----
    unsigned u[16];
    float fsum = 0.f, fsum2 = 0.f, fmax = -CUDART_INF_F;
    #pragma unroll
    for (int it = 0; it < 4; it++) {
        float4 v = __ldcs(&sp4[tid + it*256]);
        float comp[4] = {v.x, v.y, v.z, v.w};
        #pragma unroll
        for (int c = 0; c < 4; c++) {
            fsum += comp[c];
            fsum2 = fmaf(comp[c], comp[c], fsum2);
            fmax = fmaxf(fmax, comp[c]);
            u[it*4 + c] = ordf(comp[c]);
        }
    }
    #pragma unroll
    for (int o = 16; o; o >>= 1) {
        fsum  += __shfl_xor_sync(0xffffffffu, fsum,  o);
        fsum2 += __shfl_xor_sync(0xffffffffu, fsum2, o);
        fmax   = fmaxf(fmax, __shfl_xor_sync(0xffffffffu, fmax, o));
    }
    if (lane == 0) { warrf[w] = fsum; warrf[8+w] = fsum2; warrf[16+w] = fmax; }
    __syncthreads();
    float ts = 0.f, ts2 = 0.f, m = -CUDART_INF_F;
    #pragma unroll
    for (int q = 0; q < 8; q++) {
        ts += warrf[q]; ts2 += warrf[8+q]; m = fmaxf(m, warrf[16+q]);
    }
    float mu = ts * (1.f/N_);
    float var = ts2 * (1.f/N_) - mu*mu;
    float sigma = sqrtf(fmaxf(var, 0.f));

    // ---- threshold: mu + 1.40*sigma, scan-counted & adjusted ----
    float t_f = fmaf(1.40f, sigma, mu);
    unsigned t = ordf(t_f);
    int mypos = 0;
    int nc = scan_count(u, t, wtt, lane, w, &mypos);
    {
        float step = 0.5f*sigma + 1e-20f;
        int guard = 0;
        while (nc < TK_ && guard < 48) {
            t_f -= step; step *= 2.f;
            t = ordf(t_f);
            nc = scan_count(u, t, wtt, lane, w, &mypos);
            guard++;
        }
    }

    unsigned ut = 0;            // cold-path u threshold
    int eq_g = 0, need_g = 0;
    bool direct_tie = false;

    if (nc > CANDMAX_) {
        // freak path: bisect in uint space for a bracket with TK<=c<=CANDMAX
        unsigned lo = t, hi = ordf(m);
        int chi = block_count_ge(u, hi, wtt, lane, w);
        if (chi >= TK_) {
            ut = hi; eq_g = chi; need_g = TK_;
            direct_tie = true;
        } else {
            bool done = false;
            while (hi - lo > 1 && !done) {
                unsigned mid = lo + ((hi - lo) >> 1);
                int cm = block_count_ge(u, mid, wtt, lane, w);
                if (cm > CANDMAX_) lo = mid;
                else if (cm < TK_) hi = mid;
                else { t = mid; done = true; }
            }
            if (!done) {
                ut = lo;
                int gt2 = block_count_ge(u, lo + 1, wtt, lane, w);
                eq_g = block_count_ge(u, lo, wtt, lane, w) - gt2;
                need_g = TK_ - gt2;
                direct_tie = true;
            } else {
                nc = scan_count(u, t, wtt, lane, w, &mypos);
            }
        }
    }

    float wsel = 0.f;   // this thread's share of the softmax denominator

    if (!direct_tie) {
        // ---- write candidate KEYS at scanned offsets (no ballots/atomics) ----
        {
            int p = mypos;
            #pragma unroll
            for (int k = 0; k < 16; k++) {
                if (u[k] >= t) {
                    int idx = (tid + (k >> 2)*256)*4 + (k & 3);
                    cand[p++] = ((ull)u[k] << 12) | (unsigned)(4095 - idx);
                }
            }
        }
        __syncthreads();

        // ---- radix select over candidate keys; early-exit guaranteed ----
        ull kprefix = 0, pmask = 0;
        int kth = TK_;
        bool resolved = false;
        #pragma unroll
        for (int p = 0; p < 5 && !resolved; p++) {
            int sh = 36 - p*8;
            hist[tid] = 0;
            __syncthreads();
            for (int i = tid; i < nc; i += 256) {     // no sync intrinsics inside
                ull kv = cand[i];
                if ((kv & pmask) == kprefix)
                    atomicAdd(&hist[(unsigned)(kv >> sh) & 0xFFu], 1u);
            }
            __syncthreads();
            bin_select8(hist, wtt, ctrl, tid, lane, w, kth);
            kprefix |= ((ull)ctrl[0] << sh);
            kth = (int)ctrl[2];
            int bincnt = (int)ctrl[3];
            pmask |= (0xFFull << sh);

            if (bincnt <= EXTMAX_) {
                // compact bin members, uniform trip count (sync-safe)
                if (tid == 0) scnt[3] = 0;
                __syncthreads();
                int padded = (nc + 255) & ~255;
                for (int i = tid; i < padded; i += 256) {
                    ull kv = (i < nc) ? cand[i] : 0ull;
                    bool pr = (i < nc) && ((kv & pmask) == kprefix);
                    unsigned bal = __ballot_sync(0xffffffffu, pr);
                    int base = 0;
                    if (lane == 0 && bal) base = (int)atomicAdd(&scnt[3], (unsigned)__popc(bal));
                    base = __shfl_sync(0xffffffffu, base, 0);
                    if (pr) cext[base + __popc(bal & ((1u << lane) - 1u))] = kv;
                }
                __syncthreads();
                int ce = (int)scnt[3];   // == bincnt, keys distinct
                if (tid < ce) {
                    ull ki = cext[tid];
                    int gt = 0;
                    for (int j = 0; j < ce; j++) gt += (cext[j] > ki);
                    if (gt == kth - 1) skey = ki;      // exact k-th largest key
                }
                __syncthreads();
                resolved = true;
            }
        }
        ull ut_key = skey;

        // ---- selected = candidates with key >= ut_key (exactly TK) ----
        {
            int padded = (nc + 255) & ~255;
            for (int i = tid; i < padded; i += 256) {
                ull kv = (i < nc) ? cand[i] : 0ull;
                bool pr = (i < nc) && (kv >= ut_key);
                unsigned bal = __ballot_sync(0xffffffffu, pr);
                int base = 0;
                if (lane == 0 && bal) base = (int)atomicAdd(&scnt[1], (unsigned)__popc(bal));
                base = __shfl_sync(0xffffffffu, base, 0);
                if (pr) {
                    int pos = base + __popc(bal & ((1u << lane) - 1u));
                    float wt = __expf(iordf((unsigned)(kv >> 12)) - m);
                    selkw[pos] = ((ull)__float_as_uint(wt) << 32)
                               | (unsigned)(4095 - (int)(kv & 0xFFFull));
                    wsel += wt;
                }
            }
        }
    } else {
        // ---- cold path: massive ties at u == ut ----
        #pragma unroll
        for (int it = 0; it < 4; it++) {
            #pragma unroll
            for (int cc = 0; cc < 4; cc++) {
                unsigned uv = u[it*4 + cc];
                bool pg = (uv > ut), pe = (uv == ut);
                unsigned balg = __ballot_sync(0xffffffffu, pg);
                int baseg = 0;
                if (lane == 0 && balg) baseg = (int)atomicAdd(&scnt[1], (unsigned)__popc(balg));
                baseg = __shfl_sync(0xffffffffu, baseg, 0);
                if (pg) {
                    int pos = baseg + __popc(balg & ((1u << lane) - 1u));
                    float wt = __expf(iordf(uv) - m);
                    selkw[pos] = ((ull)__float_as_uint(wt) << 32)
                               | (unsigned)((tid + it*256)*4 + cc);
                    wsel += wt;
                }
                unsigned bale = __ballot_sync(0xffffffffu, pe);
                int basee = 0;
                if (lane == 0 && bale) basee = (int)atomicAdd(&scnt[2], (unsigned)__popc(bale));
                basee = __shfl_sync(0xffffffffu, basee, 0);
                if (pe) {
                    int pos = basee + __popc(bale & ((1u << lane) - 1u));
                    if (pos < 256) eqidx[pos] = (tid + it*256)*4 + cc;
                }
            }
        }
        __syncthreads();
        if (tid == 0) {
            int ecnt = (int)scnt[2]; if (ecnt > 256) ecnt = 256;
            float wt_eq = __expf(iordf(ut) - m);
            int base = TK_ - need_g;
            for (int a = 0; a < need_g; a++) {
                int bm2 = 0x7FFFFFFF, bi = -1;
                for (int e2 = 0; e2 < ecnt; e2++)
                    if (eqidx[e2] < bm2) { bm2 = eqidx[e2]; bi = e2; }
                eqidx[bi] = 0x7FFFFFFF;
                selkw[base + a] = ((ull)__float_as_uint(wt_eq) << 32) | (unsigned)bm2;
            }
            wsel += (float)need_g * wt_eq;
        }
    }

    // ---- block-reduce the softmax denominator ----
    #pragma unroll
    for (int o = 16; o; o >>= 1) wsel += __shfl_xor_sync(0xffffffffu, wsel, o);
    __syncthreads();                      // selkw complete; warrf reusable
    if (lane == 0) warrf[w] = wsel;
    __syncthreads();
    float wtot = 0.f;
    #pragma unroll
    for (int q = 0; q < 8; q++) wtot += warrf[q];
    float inv = 1.f / wtot;

    // ---- vectorized AV: warp w covers entries w*32..w*32+31 ----
    {
        int g = lane >> 3, sub = lane & 7;
        float4 a4 = make_float4(0.f, 0.f, 0.f, 0.f);
        #pragma unroll
        for (int r = 0; r < 8; r++) {
            int e = w*32 + r*4 + g;
            ull kw = selkw[e];                         // one LDS.64
            int j = (int)(unsigned)(kw & 0xFFFFFFFFull);
            float wt = __uint_as_float((unsigned)(kw >> 32));
            float4 vv = *(const float4*)&vp[(size_t)j*HD_ + sub*4];
            a4.x = fmaf(wt, vv.x, a4.x);
            a4.y = fmaf(wt, vv.y, a4.y);
            a4.z = fmaf(wt, vv.z, a4.z);
            a4.w = fmaf(wt, vv.w, a4.w);
        }
        #pragma unroll
        for (int off = 8; off <= 16; off <<= 1) {
            a4.x += __shfl_xor_sync(0xffffffffu, a4.x, off);
            a4.y += __shfl_xor_sync(0xffffffffu, a4.y, off);
            a4.z += __shfl_xor_sync(0xffffffffu, a4.z, off);
            a4.w += __shfl_xor_sync(0xffffffffu, a4.w, off);
        }
        if (g == 0) ((float4*)racc)[w*8 + sub] = a4;
    }
    __syncthreads();
    if (tid < HD_) {
        float a = 0.f;
        #pragma unroll
        for (int q = 0; q < 8; q++) a += racc[q*HD_ + tid];
        int head = bh & 3, bb = bh >> 2;
        g_att[((size_t)(bb*C_ + head*HD_ + tid)) * N_ + n] = a * inv;
    }
}

// ================= proj + residual =================
__global__ void __launch_bounds__(256) proj_kernel(const float* __restrict__ x,
                                                   const float* __restrict__ W,
                                                   const float* __restrict__ bias,
                                                   float* __restrict__ out) {
    __shared__ float as_[C_*64];
    int n0 = blockIdx.x * 64, bb = blockIdx.y;
    int tid = threadIdx.x;
    const float* ap = g_att + (size_t)bb * C_ * N_;
    for (int i = tid; i < C_*64; i += 256) {
        int c = i >> 6, nl = i & 63;
        as_[i] = ap[(size_t)c*N_ + n0 + nl];
    }
    __syncthreads();

    int nq = tid & 3, og = tid >> 2;
    float acc[2][16];
    #pragma unroll
    for (int k = 0; k < 2; k++)
        #pragma unroll
        for (int j = 0; j < 16; j++) acc[k][j] = 0.f;

    const float4* as4 = (const float4*)as_;
    for (int c = 0; c < C_; c++) {
        float4 h0 = as4[c*16 + nq*4 + 0];
        float4 h1 = as4[c*16 + nq*4 + 1];
        float4 h2 = as4[c*16 + nq*4 + 2];
        float4 h3 = as4[c*16 + nq*4 + 3];
        float hv[16] = {h0.x,h0.y,h0.z,h0.w, h1.x,h1.y,h1.z,h1.w,
                        h2.x,h2.y,h2.z,h2.w, h3.x,h3.y,h3.z,h3.w};
        #pragma unroll
        for (int k = 0; k < 2; k++) {
            float wv = W[(size_t)(og + 64*k)*C_ + c];
            #pragma unroll
            for (int j = 0; j < 16; j++) acc[k][j] += wv * hv[j];
        }
    }
    #pragma unroll
    for (int k = 0; k < 2; k++) {
        int o = og + 64*k;
        float bv = bias[o];
        size_t base = ((size_t)bb*C_ + o)*N_ + n0 + nq*16;
        #pragma unroll
        for (int j4 = 0; j4 < 4; j4++) {
            float4 xi = *(const float4*)&x[base + j4*4];
            float4 r;
            r.x = acc[k][j4*4+0] + bv + xi.x;
            r.y = acc[k][j4*4+1] + bv + xi.y;
            r.z = acc[k][j4*4+2] + bv + xi.z;
            r.w = acc[k][j4*4+3] + bv + xi.w;
            *(float4*)&out[base + j4*4] = r;
        }
    }
}

// ================= launch =================
extern "C" void kernel_launch(void* const* d_in, const int* in_sizes, int n_in,
                              void* d_out, int out_size) {
    const float* x      = (const float*)d_in[0];
    const float* gn_w   = (const float*)d_in[1];
    const float* gn_b   = (const float*)d_in[2];
    const float* qkv_w  = (const float*)d_in[3];
    const float* qkv_b  = (const float*)d_in[4];
    const float* proj_w = (const float*)d_in[5];
    const float* proj_b = (const float*)d_in[6];
    float* out = (float*)d_out;

    gn_kernel    <<<B_*GR_, 256>>>(x, gn_w, gn_b);
    qkv_kernel   <<<dim3(N_/64, B_), 256>>>(qkv_w, qkv_b);
    score_kernel <<<dim3(N_/128, N_/128, B_*NH_), 256>>>();
    select_kernel<<<dim3(N_, B_*NH_), 256>>>();
    proj_kernel  <<<dim3(N_/64, B_), 256>>>(x, proj_w, proj_b, out);
}

// round 15
// speedup vs baseline: 1.3601x; 1.3601x over previous
#include <cuda_runtime.h>
#include <math_constants.h>
#include <stdint.h>

#define B_    2
#define C_    128
#define N_    4096
#define GR_   32
#define CPG_  4
#define NH_   4
#define HD_   32
#define TK_   256
#define EPS_  1e-5f
#define SCALE_ 0.17677669529663689f   // 32^-0.5
#define CANDMAX_ 1024
#define EXTMAX_  64

typedef unsigned long long ull;

// -------- scratch (device globals; no allocation allowed) --------
static __device__ float g_h[B_*C_*N_];
static __device__ float g_q[B_*NH_*N_*HD_];
static __device__ float g_k[B_*NH_*N_*HD_];
static __device__ float g_v[B_*NH_*N_*HD_];
static __device__ float g_att[B_*C_*N_];
static __device__ float g_scores[(size_t)B_*NH_*N_*N_];  // 512 MB

__device__ __forceinline__ unsigned ordf(float f) {
    unsigned u = __float_as_uint(f);
    return (u & 0x80000000u) ? ~u : (u | 0x80000000u);
}
__device__ __forceinline__ float iordf(unsigned u) {
    return __uint_as_float((u & 0x80000000u) ? (u ^ 0x80000000u) : ~u);
}

// ---- packed fp32x2 helpers (SASS FFMA2: PTX-only, bit-identical to 2x FFMA) ----
__device__ __forceinline__ ull pack2(float lo, float hi) {
    ull r; asm("mov.b64 %0, {%1, %2};" : "=l"(r) : "f"(lo), "f"(hi)); return r;
}
__device__ __forceinline__ void unpack2(float& lo, float& hi, ull v) {
    asm("mov.b64 {%0, %1}, %2;" : "=f"(lo), "=f"(hi) : "l"(v));
}
__device__ __forceinline__ void fma2(ull& d, ull a, ull b) {
    asm("fma.rn.f32x2 %0, %1, %2, %3;" : "=l"(d) : "l"(a), "l"(b), "l"(d));
}

// ================= GroupNorm =================
__global__ void __launch_bounds__(256) gn_kernel(const float* __restrict__ x,
                                                 const float* __restrict__ w,
                                                 const float* __restrict__ b) {
    int bg = blockIdx.x;
    int bb = bg / GR_, g = bg % GR_;
    const float* xp = x + ((size_t)bb*C_ + g*CPG_) * N_;
    float*       hp = g_h + ((size_t)bb*C_ + g*CPG_) * N_;
    int tid = threadIdx.x;

    float s = 0.f, s2 = 0.f;
    for (int i = tid; i < CPG_*N_; i += 256) {
        float v = xp[i];
        s += v; s2 += v*v;
    }
    __shared__ float rs[8], rs2[8];
    __shared__ float mu_s, rstd_s;
    #pragma unroll
    for (int o = 16; o; o >>= 1) {
        s  += __shfl_down_sync(0xffffffffu, s,  o);
        s2 += __shfl_down_sync(0xffffffffu, s2, o);
    }
    if ((tid & 31) == 0) { rs[tid>>5] = s; rs2[tid>>5] = s2; }
    __syncthreads();
    if (tid == 0) {
        float t = 0.f, t2 = 0.f;
        #pragma unroll
        for (int i = 0; i < 8; i++) { t += rs[i]; t2 += rs2[i]; }
        float inv = 1.f / (float)(CPG_*N_);
        float mu = t * inv;
        float var = t2 * inv - mu*mu;
        mu_s = mu;
        rstd_s = rsqrtf(var + EPS_);
    }
    __syncthreads();
    float mu = mu_s, rstd = rstd_s;
    for (int i = tid; i < CPG_*N_; i += 256) {
        int c = g*CPG_ + i / N_;
        hp[i] = (xp[i] - mu) * rstd * w[c] + b[c];
    }
}

// ================= QKV GEMM =================
__global__ void __launch_bounds__(256) qkv_kernel(const float* __restrict__ W,
                                                  const float* __restrict__ bias) {
    __shared__ float hs[C_*64];
    int n0 = blockIdx.x * 64;
    int bb = blockIdx.y;
    int tid = threadIdx.x;
    const float* hp = g_h + (size_t)bb * C_ * N_;
    for (int i = tid; i < C_*64; i += 256) {
        int c = i >> 6, nl = i & 63;
        hs[i] = hp[(size_t)c*N_ + n0 + nl];
    }
    __syncthreads();

    int nq = tid & 3;
    int og = tid >> 2;
    float acc[6][16];
    #pragma unroll
    for (int k = 0; k < 6; k++)
        #pragma unroll
        for (int j = 0; j < 16; j++) acc[k][j] = 0.f;

    const float4* hs4 = (const float4*)hs;
    for (int c = 0; c < C_; c++) {
        float4 h0 = hs4[c*16 + nq*4 + 0];
        float4 h1 = hs4[c*16 + nq*4 + 1];
        float4 h2 = hs4[c*16 + nq*4 + 2];
        float4 h3 = hs4[c*16 + nq*4 + 3];
        float hv[16] = {h0.x,h0.y,h0.z,h0.w, h1.x,h1.y,h1.z,h1.w,
                        h2.x,h2.y,h2.z,h2.w, h3.x,h3.y,h3.z,h3.w};
        #pragma unroll
        for (int k = 0; k < 6; k++) {
            float wv = W[(size_t)(og + 64*k)*C_ + c];
            #pragma unroll
            for (int j = 0; j < 16; j++) acc[k][j] += wv * hv[j];
        }
    }
    #pragma unroll
    for (int k = 0; k < 6; k++) {
        int o = og + 64*k;
        int which = o >> 7, r = o & 127;
        int head = r >> 5, d = r & 31;
        float* dst = (which == 0) ? g_q : ((which == 1) ? g_k : g_v);
        dst += ((size_t)(bb*NH_ + head) * N_) * HD_ + d;
        float bv = bias[o];
        #pragma unroll
        for (int j = 0; j < 16; j++)
            dst[(size_t)(n0 + nq*16 + j) * HD_] = acc[k][j] + bv;
    }
}

// ================= scores = scale * Q K^T (packed f32x2 FMA) =================
__global__ void __launch_bounds__(256) score_kernel() {
    __shared__ float qs[HD_*128];
    __shared__ float ks[HD_*128];
    int bh = blockIdx.z;
    int i0 = blockIdx.y * 128, j0 = blockIdx.x * 128;
    const float* qp = g_q + (size_t)bh * N_ * HD_;
    const float* kp = g_k + (size_t)bh * N_ * HD_;
    int tid = threadIdx.x;

    for (int i = tid; i < 1024; i += 256) {
        int row = i >> 3, d4 = i & 7;
        float4 a = *(const float4*)&qp[(size_t)(i0 + row)*HD_ + d4*4];
        float4 b = *(const float4*)&kp[(size_t)(j0 + row)*HD_ + d4*4];
        int c0 = d4 * 4;
        qs[(c0+0)*128 + row] = a.x; qs[(c0+1)*128 + row] = a.y;
        qs[(c0+2)*128 + row] = a.z; qs[(c0+3)*128 + row] = a.w;
        ks[(c0+0)*128 + row] = b.x; ks[(c0+1)*128 + row] = b.y;
        ks[(c0+2)*128 + row] = b.z; ks[(c0+3)*128 + row] = b.w;
    }
    __syncthreads();

    int tx = tid & 15, ty = tid >> 4;
    const float4* qs4 = (const float4*)qs;
    const float4* ks4 = (const float4*)ks;
    ull acc2[8][4];
    #pragma unroll
    for (int r = 0; r < 8; r++)
        #pragma unroll
        for (int c = 0; c < 4; c++) acc2[r][c] = 0ull;

    #pragma unroll
    for (int kk = 0; kk < HD_; kk++) {
        float4 aL = qs4[kk*32 + ty];
        float4 aH = qs4[kk*32 + 16 + ty];
        float4 bL = ks4[kk*32 + tx];
        float4 bH = ks4[kk*32 + 16 + tx];
        ull av2[8] = {pack2(aL.x,aL.x), pack2(aL.y,aL.y), pack2(aL.z,aL.z), pack2(aL.w,aL.w),
                      pack2(aH.x,aH.x), pack2(aH.y,aH.y), pack2(aH.z,aH.z), pack2(aH.w,aH.w)};
        ull bv2[4] = {pack2(bL.x,bL.y), pack2(bL.z,bL.w),
                      pack2(bH.x,bH.y), pack2(bH.z,bH.w)};
        #pragma unroll
        for (int r = 0; r < 8; r++)
            #pragma unroll
            for (int c = 0; c < 4; c++)
                fma2(acc2[r][c], av2[r], bv2[c]);
    }

    float* sp = g_scores + (size_t)bh * N_ * N_;
    #pragma unroll
    for (int r = 0; r < 8; r++) {
        int i = i0 + ((r < 4) ? (ty*4 + r) : (64 + ty*4 + (r - 4)));
        #pragma unroll
        for (int half = 0; half < 2; half++) {
            int j = j0 + half*64 + tx*4;
            float e0, e1, e2, e3;
            unpack2(e0, e1, acc2[r][half*2 + 0]);
            unpack2(e2, e3, acc2[r][half*2 + 1]);
            float4 o;
            o.x = e0 * SCALE_;
            o.y = e1 * SCALE_;
            o.z = e2 * SCALE_;
            o.w = e3 * SCALE_;
            __stcs((float4*)&sp[(size_t)i*N_ + j], o);
        }
    }
}

// ---- block count of (u[k] >= t) over all 4096 register-resident values ----
__device__ __forceinline__ int block_count_ge(const unsigned* u, unsigned t,
                                              volatile unsigned* warru,
                                              int lane, int w) {
    int cnt = 0;
    #pragma unroll
    for (int k = 0; k < 16; k++) cnt += (u[k] >= t) ? 1 : 0;
    cnt = __reduce_add_sync(0xffffffffu, (unsigned)cnt);
    __syncthreads();
    if (lane == 0) warru[w] = (unsigned)cnt;
    __syncthreads();
    int c = 0;
    #pragma unroll
    for (int q = 0; q < 8; q++) c += (int)warru[q];
    return c;
}

// ---- 256-bin suffix selection; writes ctrl[0]=bin, ctrl[2]=kth', ctrl[3]=bincnt ----
__device__ __forceinline__ void bin_select8(unsigned* hist, unsigned* wtt,
                                            unsigned* ctrl, int tid, int lane,
                                            int w, int kth) {
    unsigned c = hist[tid];
    unsigned s = c;
    #pragma unroll
    for (int off = 1; off < 32; off <<= 1) {
        unsigned o = __shfl_down_sync(0xffffffffu, s, off);
        if (lane + off < 32) s += o;
    }
    if (lane == 0) wtt[w] = s;
    __syncthreads();
    unsigned add = 0;
    #pragma unroll
    for (int q = 0; q < 8; q++) if (q > w) add += wtt[q];
    unsigned Sincl = s + add;
    unsigned Sexcl = Sincl - c;
    if (Sexcl < (unsigned)kth && (unsigned)kth <= Sincl) {
        ctrl[0] = (unsigned)tid;
        ctrl[2] = (unsigned)kth - Sexcl;
        ctrl[3] = c;
    }
    __syncthreads();
}

// ================= top-256 select + softmax AV =====================
// 44-bit keys (u<<12)|(4095-idx) == lax.top_k semantics (lowest-index
// tie-break), no tie machinery on the hot path. Ballot-compacted candidates
// (coalesced smem writes), radix with early-exit brute rank, packed (wt,idx).
__global__ void __launch_bounds__(256) select_kernel() {
    __shared__ ull      cand[CANDMAX_];   // 8 KB candidate keys
    __shared__ ull      cext[EXTMAX_];
    __shared__ ull      skey;
    __shared__ ull      selkw[TK_];       // 2 KB packed (wt,idx)
    __shared__ unsigned hist[256];        // 1 KB
    __shared__ float    warrf[3*8];
    __shared__ unsigned warru[8];
    __shared__ unsigned wtt[8];
    __shared__ unsigned ctrl[8];
    __shared__ unsigned scnt[4];
    __shared__ int      eqidx[256];
    __shared__ __align__(16) float racc[8*HD_];

    int n = blockIdx.x, bh = blockIdx.y;
    const float4* sp4 = (const float4*)(g_scores + (size_t)bh*N_*N_ + (size_t)n*N_);
    const float* vp = g_v + (size_t)bh*N_*HD_;
    int tid = threadIdx.x;
    int lane = tid & 31, w = tid >> 5;

    if (tid < 4) scnt[tid] = 0;

    // ---- load row into registers (ordf) + sum/sum2/max ----
    unsigned u[16];
    float fsum = 0.f, fsum2 = 0.f, fmax = -CUDART_INF_F;
    #pragma unroll
    for (int it = 0; it < 4; it++) {
        float4 v = __ldcs(&sp4[tid + it*256]);
        float comp[4] = {v.x, v.y, v.z, v.w};
        #pragma unroll
        for (int c = 0; c < 4; c++) {
            fsum += comp[c];
            fsum2 = fmaf(comp[c], comp[c], fsum2);
            fmax = fmaxf(fmax, comp[c]);
            u[it*4 + c] = ordf(comp[c]);
        }
    }
    #pragma unroll
    for (int o = 16; o; o >>= 1) {
        fsum  += __shfl_xor_sync(0xffffffffu, fsum,  o);
        fsum2 += __shfl_xor_sync(0xffffffffu, fsum2, o);
        fmax   = fmaxf(fmax, __shfl_xor_sync(0xffffffffu, fmax, o));
    }
    if (lane == 0) { warrf[w] = fsum; warrf[8+w] = fsum2; warrf[16+w] = fmax; }
    __syncthreads();
    float ts = 0.f, ts2 = 0.f, m = -CUDART_INF_F;
    #pragma unroll
    for (int q = 0; q < 8; q++) {
        ts += warrf[q]; ts2 += warrf[8+q]; m = fmaxf(m, warrf[16+q]);
    }
    float mu = ts * (1.f/N_);
    float var = ts2 * (1.f/N_) - mu*mu;
    float sigma = sqrtf(fmaxf(var, 0.f));

    // ---- threshold: mu + 1.40*sigma (E[count]~330), verified & adjusted ----
    float t_f = fmaf(1.40f, sigma, mu);
    unsigned t = ordf(t_f);
    int c = block_count_ge(u, t, warru, lane, w);
    {
        float step = 0.5f*sigma + 1e-20f;
        int guard = 0;
        while (c < TK_ && guard < 48) {
            t_f -= step; step *= 2.f;
            t = ordf(t_f);
            c = block_count_ge(u, t, warru, lane, w);
            guard++;
        }
    }

    unsigned ut = 0;            // cold-path u threshold
    int eq_g = 0, need_g = 0;
    bool direct_tie = false;

    if (c > CANDMAX_) {
        // freak path: bisect in uint space for a bracket with TK<=c<=CANDMAX
        unsigned lo = t, hi = ordf(m);
        int chi = block_count_ge(u, hi, warru, lane, w);
        if (chi >= TK_) {
            ut = hi; eq_g = chi; need_g = TK_;
            direct_tie = true;
        } else {
            bool done = false;
            while (hi - lo > 1 && !done) {
                unsigned mid = lo + ((hi - lo) >> 1);
                int cm = block_count_ge(u, mid, warru, lane, w);
                if (cm > CANDMAX_) lo = mid;
                else if (cm < TK_) hi = mid;
                else { t = mid; c = cm; done = true; }
            }
            if (!done) {
                ut = lo;
                int gt2 = block_count_ge(u, lo + 1, warru, lane, w);
                eq_g = block_count_ge(u, lo, warru, lane, w) - gt2;
                need_g = TK_ - gt2;
                direct_tie = true;
            }
        }
    }

    float wsel = 0.f;   // this thread's share of the softmax denominator

    if (!direct_tie) {
        // ---- ballot-compact candidate KEYS (coalesced smem writes) ----
        #pragma unroll
        for (int k = 0; k < 16; k++) {
            bool pred = (u[k] >= t);
            unsigned bal = __ballot_sync(0xffffffffu, pred);
            int base = 0;
            if (lane == 0 && bal) base = (int)atomicAdd(&scnt[0], (unsigned)__popc(bal));
            base = __shfl_sync(0xffffffffu, base, 0);
            if (pred) {
                int idx = (tid + (k >> 2)*256)*4 + (k & 3);
                cand[base + __popc(bal & ((1u << lane) - 1u))] =
                    ((ull)u[k] << 12) | (unsigned)(4095 - idx);
            }
        }
        __syncthreads();
        int nc = (int)scnt[0];

        // ---- radix select over candidate keys; early-exit guaranteed ----
        ull kprefix = 0, pmask = 0;
        int kth = TK_;
        bool resolved = false;
        #pragma unroll
        for (int p = 0; p < 5 && !resolved; p++) {
            int sh = 36 - p*8;
            hist[tid] = 0;
            __syncthreads();
            for (int i = tid; i < nc; i += 256) {     // no sync intrinsics inside
                ull kv = cand[i];
                if ((kv & pmask) == kprefix)
                    atomicAdd(&hist[(unsigned)(kv >> sh) & 0xFFu], 1u);
            }
            __syncthreads();
            bin_select8(hist, wtt, ctrl, tid, lane, w, kth);
            kprefix |= ((ull)ctrl[0] << sh);
            kth = (int)ctrl[2];
            int bincnt = (int)ctrl[3];
            pmask |= (0xFFull << sh);

            if (bincnt <= EXTMAX_) {
                // compact bin members, uniform trip count (sync-safe)
                if (tid == 0) scnt[3] = 0;
                __syncthreads();
                int padded = (nc + 255) & ~255;
                for (int i = tid; i < padded; i += 256) {
                    ull kv = (i < nc) ? cand[i] : 0ull;
                    bool pr = (i < nc) && ((kv & pmask) == kprefix);
                    unsigned bal = __ballot_sync(0xffffffffu, pr);
                    int base = 0;
                    if (lane == 0 && bal) base = (int)atomicAdd(&scnt[3], (unsigned)__popc(bal));
                    base = __shfl_sync(0xffffffffu, base, 0);
                    if (pr) cext[base + __popc(bal & ((1u << lane) - 1u))] = kv;
                }
                __syncthreads();
                int ce = (int)scnt[3];   // == bincnt, keys distinct
                if (tid < ce) {
                    ull ki = cext[tid];
                    int gt = 0;
                    for (int j = 0; j < ce; j++) gt += (cext[j] > ki);
                    if (gt == kth - 1) skey = ki;      // exact k-th largest key
                }
                __syncthreads();
                resolved = true;
            }
        }
        ull ut_key = skey;

        // ---- selected = candidates with key >= ut_key (exactly TK) ----
        {
            int padded = (nc + 255) & ~255;
            for (int i = tid; i < padded; i += 256) {
                ull kv = (i < nc) ? cand[i] : 0ull;
                bool pr = (i < nc) && (kv >= ut_key);
                unsigned bal = __ballot_sync(0xffffffffu, pr);
                int base = 0;
                if (lane == 0 && bal) base = (int)atomicAdd(&scnt[1], (unsigned)__popc(bal));
                base = __shfl_sync(0xffffffffu, base, 0);
                if (pr) {
                    int pos = base + __popc(bal & ((1u << lane) - 1u));
                    float wt = __expf(iordf((unsigned)(kv >> 12)) - m);
                    selkw[pos] = ((ull)__float_as_uint(wt) << 32)
                               | (unsigned)(4095 - (int)(kv & 0xFFFull));
                    wsel += wt;
                }
            }
        }
    } else {
        // ---- cold path: massive ties at u == ut ----
        #pragma unroll
        for (int it = 0; it < 4; it++) {
            #pragma unroll
            for (int cc = 0; cc < 4; cc++) {
                unsigned uv = u[it*4 + cc];
                bool pg = (uv > ut), pe = (uv == ut);
                unsigned balg = __ballot_sync(0xffffffffu, pg);
                int baseg = 0;
                if (lane == 0 && balg) baseg = (int)atomicAdd(&scnt[1], (unsigned)__popc(balg));
                baseg = __shfl_sync(0xffffffffu, baseg, 0);
                if (pg) {
                    int pos = baseg + __popc(balg & ((1u << lane) - 1u));
                    float wt = __expf(iordf(uv) - m);
                    selkw[pos] = ((ull)__float_as_uint(wt) << 32)
                               | (unsigned)((tid + it*256)*4 + cc);
                    wsel += wt;
                }
                unsigned bale = __ballot_sync(0xffffffffu, pe);
                int basee = 0;
                if (lane == 0 && bale) basee = (int)atomicAdd(&scnt[2], (unsigned)__popc(bale));
                basee = __shfl_sync(0xffffffffu, basee, 0);
                if (pe) {
                    int pos = basee + __popc(bale & ((1u << lane) - 1u));
                    if (pos < 256) eqidx[pos] = (tid + it*256)*4 + cc;
                }
            }
        }
        __syncthreads();
        if (tid == 0) {
            int ecnt = (int)scnt[2]; if (ecnt > 256) ecnt = 256;
            float wt_eq = __expf(iordf(ut) - m);
            int base = TK_ - need_g;
            for (int a = 0; a < need_g; a++) {
                int bm2 = 0x7FFFFFFF, bi = -1;
                for (int e2 = 0; e2 < ecnt; e2++)
                    if (eqidx[e2] < bm2) { bm2 = eqidx[e2]; bi = e2; }
                eqidx[bi] = 0x7FFFFFFF;
                selkw[base + a] = ((ull)__float_as_uint(wt_eq) << 32) | (unsigned)bm2;
            }
            wsel += (float)need_g * wt_eq;
        }
    }

    // ---- block-reduce the softmax denominator ----
    #pragma unroll
    for (int o = 16; o; o >>= 1) wsel += __shfl_xor_sync(0xffffffffu, wsel, o);
    __syncthreads();                      // selkw complete; warrf reusable
    if (lane == 0) warrf[w] = wsel;
    __syncthreads();
    float wtot = 0.f;
    #pragma unroll
    for (int q = 0; q < 8; q++) wtot += warrf[q];
    float inv = 1.f / wtot;

    // ---- vectorized AV: warp w covers entries w*32..w*32+31 ----
    {
        int g = lane >> 3, sub = lane & 7;
        float4 a4 = make_float4(0.f, 0.f, 0.f, 0.f);
        #pragma unroll
        for (int r = 0; r < 8; r++) {
            int e = w*32 + r*4 + g;
            ull kw = selkw[e];                         // one LDS.64
            int j = (int)(unsigned)(kw & 0xFFFFFFFFull);
            float wt = __uint_as_float((unsigned)(kw >> 32));
            float4 vv = *(const float4*)&vp[(size_t)j*HD_ + sub*4];
            a4.x = fmaf(wt, vv.x, a4.x);
            a4.y = fmaf(wt, vv.y, a4.y);
            a4.z = fmaf(wt, vv.z, a4.z);
            a4.w = fmaf(wt, vv.w, a4.w);
        }
        #pragma unroll
        for (int off = 8; off <= 16; off <<= 1) {
            a4.x += __shfl_xor_sync(0xffffffffu, a4.x, off);
            a4.y += __shfl_xor_sync(0xffffffffu, a4.y, off);
            a4.z += __shfl_xor_sync(0xffffffffu, a4.z, off);
            a4.w += __shfl_xor_sync(0xffffffffu, a4.w, off);
        }
        if (g == 0) ((float4*)racc)[w*8 + sub] = a4;
    }
    __syncthreads();
    if (tid < HD_) {
        float a = 0.f;
        #pragma unroll
        for (int q = 0; q < 8; q++) a += racc[q*HD_ + tid];
        int head = bh & 3, bb = bh >> 2;
        g_att[((size_t)(bb*C_ + head*HD_ + tid)) * N_ + n] = a * inv;
    }
}

// ================= proj + residual =================
__global__ void __launch_bounds__(256) proj_kernel(const float* __restrict__ x,
                                                   const float* __restrict__ W,
                                                   const float* __restrict__ bias,
                                                   float* __restrict__ out) {
    __shared__ float as_[C_*64];
    int n0 = blockIdx.x * 64, bb = blockIdx.y;
    int tid = threadIdx.x;
    const float* ap = g_att + (size_t)bb * C_ * N_;
    for (int i = tid; i < C_*64; i += 256) {
        int c = i >> 6, nl = i & 63;
        as_[i] = ap[(size_t)c*N_ + n0 + nl];
    }
    __syncthreads();

    int nq = tid & 3, og = tid >> 2;
    float acc[2][16];
    #pragma unroll
    for (int k = 0; k < 2; k++)
        #pragma unroll
        for (int j = 0; j < 16; j++) acc[k][j] = 0.f;

    const float4* as4 = (const float4*)as_;
    for (int c = 0; c < C_; c++) {
        float4 h0 = as4[c*16 + nq*4 + 0];
        float4 h1 = as4[c*16 + nq*4 + 1];
        float4 h2 = as4[c*16 + nq*4 + 2];
        float4 h3 = as4[c*16 + nq*4 + 3];
        float hv[16] = {h0.x,h0.y,h0.z,h0.w, h1.x,h1.y,h1.z,h1.w,
                        h2.x,h2.y,h2.z,h2.w, h3.x,h3.y,h3.z,h3.w};
        #pragma unroll
        for (int k = 0; k < 2; k++) {
            float wv = W[(size_t)(og + 64*k)*C_ + c];
            #pragma unroll
            for (int j = 0; j < 16; j++) acc[k][j] += wv * hv[j];
        }
    }
    #pragma unroll
    for (int k = 0; k < 2; k++) {
        int o = og + 64*k;
        float bv = bias[o];
        size_t base = ((size_t)bb*C_ + o)*N_ + n0 + nq*16;
        #pragma unroll
        for (int j4 = 0; j4 < 4; j4++) {
            float4 xi = *(const float4*)&x[base + j4*4];
            float4 r;
            r.x = acc[k][j4*4+0] + bv + xi.x;
            r.y = acc[k][j4*4+1] + bv + xi.y;
            r.z = acc[k][j4*4+2] + bv + xi.z;
            r.w = acc[k][j4*4+3] + bv + xi.w;
            *(float4*)&out[base + j4*4] = r;
        }
    }
}

// ================= launch =================
extern "C" void kernel_launch(void* const* d_in, const int* in_sizes, int n_in,
                              void* d_out, int out_size) {
    const float* x      = (const float*)d_in[0];
    const float* gn_w   = (const float*)d_in[1];
    const float* gn_b   = (const float*)d_in[2];
    const float* qkv_w  = (const float*)d_in[3];
    const float* qkv_b  = (const float*)d_in[4];
    const float* proj_w = (const float*)d_in[5];
    const float* proj_b = (const float*)d_in[6];
    float* out = (float*)d_out;

    gn_kernel    <<<B_*GR_, 256>>>(x, gn_w, gn_b);
    qkv_kernel   <<<dim3(N_/64, B_), 256>>>(qkv_w, qkv_b);
    score_kernel <<<dim3(N_/128, N_/128, B_*NH_), 256>>>();
    select_kernel<<<dim3(N_, B_*NH_), 256>>>();
    proj_kernel  <<<dim3(N_/64, B_), 256>>>(x, proj_w, proj_b, out);
}

// round 16
// speedup vs baseline: 1.3775x; 1.0128x over previous
#include <cuda_runtime.h>
#include <math_constants.h>
#include <stdint.h>

#define B_    2
#define C_    128
#define N_    4096
#define GR_   32
#define CPG_  4
#define NH_   4
#define HD_   32
#define TK_   256
#define EPS_  1e-5f
#define SCALE_ 0.17677669529663689f   // 32^-0.5
#define CANDMAX_ 1024
#define EXTMAX_  64

typedef unsigned long long ull;

// -------- scratch (device globals; no allocation allowed) --------
static __device__ float g_h[B_*C_*N_];
static __device__ float g_q[B_*NH_*N_*HD_];
static __device__ float g_k[B_*NH_*N_*HD_];
static __device__ float g_v[B_*NH_*N_*HD_];
static __device__ float g_att[B_*C_*N_];
static __device__ float g_scores[(size_t)B_*NH_*N_*N_];  // 512 MB

__device__ __forceinline__ unsigned ordf(float f) {
    unsigned u = __float_as_uint(f);
    return (u & 0x80000000u) ? ~u : (u | 0x80000000u);
}
__device__ __forceinline__ float iordf(unsigned u) {
    return __uint_as_float((u & 0x80000000u) ? (u ^ 0x80000000u) : ~u);
}

// ---- packed fp32x2 helpers (SASS FFMA2: PTX-only, bit-identical to 2x FFMA) ----
__device__ __forceinline__ ull pack2(float lo, float hi) {
    ull r; asm("mov.b64 %0, {%1, %2};" : "=l"(r) : "f"(lo), "f"(hi)); return r;
}
__device__ __forceinline__ void unpack2(float& lo, float& hi, ull v) {
    asm("mov.b64 {%0, %1}, %2;" : "=f"(lo), "=f"(hi) : "l"(v));
}
__device__ __forceinline__ void fma2(ull& d, ull a, ull b) {
    asm("fma.rn.f32x2 %0, %1, %2, %3;" : "=l"(d) : "l"(a), "l"(b), "l"(d));
}

// ================= GroupNorm =================
__global__ void __launch_bounds__(256) gn_kernel(const float* __restrict__ x,
                                                 const float* __restrict__ w,
                                                 const float* __restrict__ b) {
    int bg = blockIdx.x;
    int bb = bg / GR_, g = bg % GR_;
    const float* xp = x + ((size_t)bb*C_ + g*CPG_) * N_;
    float*       hp = g_h + ((size_t)bb*C_ + g*CPG_) * N_;
    int tid = threadIdx.x;

    float s = 0.f, s2 = 0.f;
    for (int i = tid; i < CPG_*N_; i += 256) {
        float v = xp[i];
        s += v; s2 += v*v;
    }
    __shared__ float rs[8], rs2[8];
    __shared__ float mu_s, rstd_s;
    #pragma unroll
    for (int o = 16; o; o >>= 1) {
        s  += __shfl_down_sync(0xffffffffu, s,  o);
        s2 += __shfl_down_sync(0xffffffffu, s2, o);
    }
    if ((tid & 31) == 0) { rs[tid>>5] = s; rs2[tid>>5] = s2; }
    __syncthreads();
    if (tid == 0) {
        float t = 0.f, t2 = 0.f;
        #pragma unroll
        for (int i = 0; i < 8; i++) { t += rs[i]; t2 += rs2[i]; }
        float inv = 1.f / (float)(CPG_*N_);
        float mu = t * inv;
        float var = t2 * inv - mu*mu;
        mu_s = mu;
        rstd_s = rsqrtf(var + EPS_);
    }
    __syncthreads();
    float mu = mu_s, rstd = rstd_s;
    for (int i = tid; i < CPG_*N_; i += 256) {
        int c = g*CPG_ + i / N_;
        hp[i] = (xp[i] - mu) * rstd * w[c] + b[c];
    }
}

// ================= QKV GEMM (smem-staged W, conflict-free broadcast) =========
// W chunk: 8 c's of all 384 o's, transposed ws[cc][o] with +1 pad.
__global__ void __launch_bounds__(256) qkv_kernel(const float* __restrict__ W,
                                                  const float* __restrict__ bias) {
    __shared__ float hs[C_*64];           // 32 KB  [c][n_local]
    __shared__ float ws[8*385];           // 12.3 KB  ws[cc*385 + o]
    int n0 = blockIdx.x * 64;
    int bb = blockIdx.y;
    int tid = threadIdx.x;
    const float* hp = g_h + (size_t)bb * C_ * N_;
    for (int i = tid; i < C_*64; i += 256) {
        int c = i >> 6, nl = i & 63;
        hs[i] = hp[(size_t)c*N_ + n0 + nl];
    }

    int nq = tid & 3;
    int og = tid >> 2;
    float acc[6][16];
    #pragma unroll
    for (int k = 0; k < 6; k++)
        #pragma unroll
        for (int j = 0; j < 16; j++) acc[k][j] = 0.f;

    const float4* hs4 = (const float4*)hs;
    for (int ch = 0; ch < 16; ch++) {
        int c0 = ch * 8;
        __syncthreads();                       // protect ws from prior compute
        // coalesced load of W[0:384][c0:c0+8] -> transposed ws
        #pragma unroll
        for (int t3 = 0; t3 < 3; t3++) {
            int i = tid + t3*256;              // 0..767 float4s
            int o = i >> 1, h = i & 1;
            float4 wv4 = *(const float4*)&W[(size_t)o*C_ + c0 + h*4];
            int ccb = h * 4;
            ws[(ccb+0)*385 + o] = wv4.x;
            ws[(ccb+1)*385 + o] = wv4.y;
            ws[(ccb+2)*385 + o] = wv4.z;
            ws[(ccb+3)*385 + o] = wv4.w;
        }
        __syncthreads();
        #pragma unroll
        for (int cc = 0; cc < 8; cc++) {
            int c = c0 + cc;
            float4 h0 = hs4[c*16 + nq*4 + 0];
            float4 h1 = hs4[c*16 + nq*4 + 1];
            float4 h2 = hs4[c*16 + nq*4 + 2];
            float4 h3 = hs4[c*16 + nq*4 + 3];
            float hv[16] = {h0.x,h0.y,h0.z,h0.w, h1.x,h1.y,h1.z,h1.w,
                            h2.x,h2.y,h2.z,h2.w, h3.x,h3.y,h3.z,h3.w};
            #pragma unroll
            for (int k = 0; k < 6; k++) {
                float wv = ws[cc*385 + og + 64*k];   // broadcast, conflict-free
                #pragma unroll
                for (int j = 0; j < 16; j++) acc[k][j] += wv * hv[j];
            }
        }
    }
    #pragma unroll
    for (int k = 0; k < 6; k++) {
        int o = og + 64*k;
        int which = o >> 7, r = o & 127;
        int head = r >> 5, d = r & 31;
        float* dst = (which == 0) ? g_q : ((which == 1) ? g_k : g_v);
        dst += ((size_t)(bb*NH_ + head) * N_) * HD_ + d;
        float bv = bias[o];
        #pragma unroll
        for (int j = 0; j < 16; j++)
            dst[(size_t)(n0 + nq*16 + j) * HD_] = acc[k][j] + bv;
    }
}

// ================= scores = scale * Q K^T (packed f32x2 FMA) =================
__global__ void __launch_bounds__(256) score_kernel() {
    __shared__ float qs[HD_*128];
    __shared__ float ks[HD_*128];
    int bh = blockIdx.z;
    int i0 = blockIdx.y * 128, j0 = blockIdx.x * 128;
    const float* qp = g_q + (size_t)bh * N_ * HD_;
    const float* kp = g_k + (size_t)bh * N_ * HD_;
    int tid = threadIdx.x;

    for (int i = tid; i < 1024; i += 256) {
        int row = i >> 3, d4 = i & 7;
        float4 a = *(const float4*)&qp[(size_t)(i0 + row)*HD_ + d4*4];
        float4 b = *(const float4*)&kp[(size_t)(j0 + row)*HD_ + d4*4];
        int c0 = d4 * 4;
        qs[(c0+0)*128 + row] = a.x; qs[(c0+1)*128 + row] = a.y;
        qs[(c0+2)*128 + row] = a.z; qs[(c0+3)*128 + row] = a.w;
        ks[(c0+0)*128 + row] = b.x; ks[(c0+1)*128 + row] = b.y;
        ks[(c0+2)*128 + row] = b.z; ks[(c0+3)*128 + row] = b.w;
    }
    __syncthreads();

    int tx = tid & 15, ty = tid >> 4;
    const float4* qs4 = (const float4*)qs;
    const float4* ks4 = (const float4*)ks;
    ull acc2[8][4];
    #pragma unroll
    for (int r = 0; r < 8; r++)
        #pragma unroll
        for (int c = 0; c < 4; c++) acc2[r][c] = 0ull;

    #pragma unroll
    for (int kk = 0; kk < HD_; kk++) {
        float4 aL = qs4[kk*32 + ty];
        float4 aH = qs4[kk*32 + 16 + ty];
        float4 bL = ks4[kk*32 + tx];
        float4 bH = ks4[kk*32 + 16 + tx];
        ull av2[8] = {pack2(aL.x,aL.x), pack2(aL.y,aL.y), pack2(aL.z,aL.z), pack2(aL.w,aL.w),
                      pack2(aH.x,aH.x), pack2(aH.y,aH.y), pack2(aH.z,aH.z), pack2(aH.w,aH.w)};
        ull bv2[4] = {pack2(bL.x,bL.y), pack2(bL.z,bL.w),
                      pack2(bH.x,bH.y), pack2(bH.z,bH.w)};
        #pragma unroll
        for (int r = 0; r < 8; r++)
            #pragma unroll
            for (int c = 0; c < 4; c++)
                fma2(acc2[r][c], av2[r], bv2[c]);
    }

    float* sp = g_scores + (size_t)bh * N_ * N_;
    #pragma unroll
    for (int r = 0; r < 8; r++) {
        int i = i0 + ((r < 4) ? (ty*4 + r) : (64 + ty*4 + (r - 4)));
        #pragma unroll
        for (int half = 0; half < 2; half++) {
            int j = j0 + half*64 + tx*4;
            float e0, e1, e2, e3;
            unpack2(e0, e1, acc2[r][half*2 + 0]);
            unpack2(e2, e3, acc2[r][half*2 + 1]);
            float4 o;
            o.x = e0 * SCALE_;
            o.y = e1 * SCALE_;
            o.z = e2 * SCALE_;
            o.w = e3 * SCALE_;
            __stcs((float4*)&sp[(size_t)i*N_ + j], o);
        }
    }
}

// ---- block count of (u[k] >= t) over all 4096 register-resident values ----
__device__ __forceinline__ int block_count_ge(const unsigned* u, unsigned t,
                                              volatile unsigned* warru,
                                              int lane, int w) {
    int cnt = 0;
    #pragma unroll
    for (int k = 0; k < 16; k++) cnt += (u[k] >= t) ? 1 : 0;
    cnt = __reduce_add_sync(0xffffffffu, (unsigned)cnt);
    __syncthreads();
    if (lane == 0) warru[w] = (unsigned)cnt;
    __syncthreads();
    int c = 0;
    #pragma unroll
    for (int q = 0; q < 8; q++) c += (int)warru[q];
    return c;
}

// ---- 256-bin suffix selection; writes ctrl[0]=bin, ctrl[2]=kth', ctrl[3]=bincnt ----
__device__ __forceinline__ void bin_select8(unsigned* hist, unsigned* wtt,
                                            unsigned* ctrl, int tid, int lane,
                                            int w, int kth) {
    unsigned c = hist[tid];
    unsigned s = c;
    #pragma unroll
    for (int off = 1; off < 32; off <<= 1) {
        unsigned o = __shfl_down_sync(0xffffffffu, s, off);
        if (lane + off < 32) s += o;
    }
    if (lane == 0) wtt[w] = s;
    __syncthreads();
    unsigned add = 0;
    #pragma unroll
    for (int q = 0; q < 8; q++) if (q > w) add += wtt[q];
    unsigned Sincl = s + add;
    unsigned Sexcl = Sincl - c;
    if (Sexcl < (unsigned)kth && (unsigned)kth <= Sincl) {
        ctrl[0] = (unsigned)tid;
        ctrl[2] = (unsigned)kth - Sexcl;
        ctrl[3] = c;
    }
    __syncthreads();
}

// ================= top-256 select + softmax AV =====================
// 44-bit keys (u<<12)|(4095-idx) == lax.top_k semantics (lowest-index
// tie-break), no tie machinery on the hot path. Ballot-compacted candidates
// (coalesced smem writes), radix with early-exit brute rank, packed (wt,idx).
__global__ void __launch_bounds__(256) select_kernel() {
    __shared__ ull      cand[CANDMAX_];   // 8 KB candidate keys
    __shared__ ull      cext[EXTMAX_];
    __shared__ ull      skey;
    __shared__ ull      selkw[TK_];       // 2 KB packed (wt,idx)
    __shared__ unsigned hist[256];        // 1 KB
    __shared__ float    warrf[3*8];
    __shared__ unsigned warru[8];
    __shared__ unsigned wtt[8];
    __shared__ unsigned ctrl[8];
    __shared__ unsigned scnt[4];
    __shared__ int      eqidx[256];
    __shared__ __align__(16) float racc[8*HD_];

    int n = blockIdx.x, bh = blockIdx.y;
    const float4* sp4 = (const float4*)(g_scores + (size_t)bh*N_*N_ + (size_t)n*N_);
    const float* vp = g_v + (size_t)bh*N_*HD_;
    int tid = threadIdx.x;
    int lane = tid & 31, w = tid >> 5;

    if (tid < 4) scnt[tid] = 0;

    // ---- load row into registers (ordf) + sum/sum2/max ----
    unsigned u[16];
    float fsum = 0.f, fsum2 = 0.f, fmax = -CUDART_INF_F;
    #pragma unroll
    for (int it = 0; it < 4; it++) {
        float4 v = __ldcs(&sp4[tid + it*256]);
        float comp[4] = {v.x, v.y, v.z, v.w};
        #pragma unroll
        for (int c = 0; c < 4; c++) {
            fsum += comp[c];
            fsum2 = fmaf(comp[c], comp[c], fsum2);
            fmax = fmaxf(fmax, comp[c]);
            u[it*4 + c] = ordf(comp[c]);
        }
    }
    #pragma unroll
    for (int o = 16; o; o >>= 1) {
        fsum  += __shfl_xor_sync(0xffffffffu, fsum,  o);
        fsum2 += __shfl_xor_sync(0xffffffffu, fsum2, o);
        fmax   = fmaxf(fmax, __shfl_xor_sync(0xffffffffu, fmax, o));
    }
    if (lane == 0) { warrf[w] = fsum; warrf[8+w] = fsum2; warrf[16+w] = fmax; }
    __syncthreads();
    float ts = 0.f, ts2 = 0.f, m = -CUDART_INF_F;
    #pragma unroll
    for (int q = 0; q < 8; q++) {
        ts += warrf[q]; ts2 += warrf[8+q]; m = fmaxf(m, warrf[16+q]);
    }
    float mu = ts * (1.f/N_);
    float var = ts2 * (1.f/N_) - mu*mu;
    float sigma = sqrtf(fmaxf(var, 0.f));

    // ---- threshold: mu + 1.40*sigma (E[count]~330), verified & adjusted ----
    float t_f = fmaf(1.40f, sigma, mu);
    unsigned t = ordf(t_f);
    int c = block_count_ge(u, t, warru, lane, w);
    {
        float step = 0.5f*sigma + 1e-20f;
        int guard = 0;
        while (c < TK_ && guard < 48) {
            t_f -= step; step *= 2.f;
            t = ordf(t_f);
            c = block_count_ge(u, t, warru, lane, w);
            guard++;
        }
    }

    unsigned ut = 0;            // cold-path u threshold
    int eq_g = 0, need_g = 0;
    bool direct_tie = false;

    if (c > CANDMAX_) {
        // freak path: bisect in uint space for a bracket with TK<=c<=CANDMAX
        unsigned lo = t, hi = ordf(m);
        int chi = block_count_ge(u, hi, warru, lane, w);
        if (chi >= TK_) {
            ut = hi; eq_g = chi; need_g = TK_;
            direct_tie = true;
        } else {
            bool done = false;
            while (hi - lo > 1 && !done) {
                unsigned mid = lo + ((hi - lo) >> 1);
                int cm = block_count_ge(u, mid, warru, lane, w);
                if (cm > CANDMAX_) lo = mid;
                else if (cm < TK_) hi = mid;
                else { t = mid; c = cm; done = true; }
            }
            if (!done) {
                ut = lo;
                int gt2 = block_count_ge(u, lo + 1, warru, lane, w);
                eq_g = block_count_ge(u, lo, warru, lane, w) - gt2;
                need_g = TK_ - gt2;
                direct_tie = true;
            }
        }
    }

    float wsel = 0.f;   // this thread's share of the softmax denominator

    if (!direct_tie) {
        // ---- ballot-compact candidate KEYS (coalesced smem writes) ----
        #pragma unroll
        for (int k = 0; k < 16; k++) {
            bool pred = (u[k] >= t);
            unsigned bal = __ballot_sync(0xffffffffu, pred);
            int base = 0;
            if (lane == 0 && bal) base = (int)atomicAdd(&scnt[0], (unsigned)__popc(bal));
            base = __shfl_sync(0xffffffffu, base, 0);
            if (pred) {
                int idx = (tid + (k >> 2)*256)*4 + (k & 3);
                cand[base + __popc(bal & ((1u << lane) - 1u))] =
                    ((ull)u[k] << 12) | (unsigned)(4095 - idx);
            }
        }
        __syncthreads();
        int nc = (int)scnt[0];

        // ---- radix select over candidate keys; early-exit guaranteed ----
        ull kprefix = 0, pmask = 0;
        int kth = TK_;
        bool resolved = false;
        #pragma unroll
        for (int p = 0; p < 5 && !resolved; p++) {
            int sh = 36 - p*8;
            hist[tid] = 0;
            __syncthreads();
            for (int i = tid; i < nc; i += 256) {     // no sync intrinsics inside
                ull kv = cand[i];
                if ((kv & pmask) == kprefix)
                    atomicAdd(&hist[(unsigned)(kv >> sh) & 0xFFu], 1u);
            }
            __syncthreads();
            bin_select8(hist, wtt, ctrl, tid, lane, w, kth);
            kprefix |= ((ull)ctrl[0] << sh);
            kth = (int)ctrl[2];
            int bincnt = (int)ctrl[3];
            pmask |= (0xFFull << sh);

            if (bincnt <= EXTMAX_) {
                // compact bin members, uniform trip count (sync-safe)
                if (tid == 0) scnt[3] = 0;
                __syncthreads();
                int padded = (nc + 255) & ~255;
                for (int i = tid; i < padded; i += 256) {
                    ull kv = (i < nc) ? cand[i] : 0ull;
                    bool pr = (i < nc) && ((kv & pmask) == kprefix);
                    unsigned bal = __ballot_sync(0xffffffffu, pr);
                    int base = 0;
                    if (lane == 0 && bal) base = (int)atomicAdd(&scnt[3], (unsigned)__popc(bal));
                    base = __shfl_sync(0xffffffffu, base, 0);
                    if (pr) cext[base + __popc(bal & ((1u << lane) - 1u))] = kv;
                }
                __syncthreads();
                int ce = (int)scnt[3];   // == bincnt, keys distinct
                if (tid < ce) {
                    ull ki = cext[tid];
                    int gt = 0;
                    for (int j = 0; j < ce; j++) gt += (cext[j] > ki);
                    if (gt == kth - 1) skey = ki;      // exact k-th largest key
                }
                __syncthreads();
                resolved = true;
            }
        }
        ull ut_key = skey;

        // ---- selected = candidates with key >= ut_key (exactly TK) ----
        {
            int padded = (nc + 255) & ~255;
            for (int i = tid; i < padded; i += 256) {
                ull kv = (i < nc) ? cand[i] : 0ull;
                bool pr = (i < nc) && (kv >= ut_key);
                unsigned bal = __ballot_sync(0xffffffffu, pr);
                int base = 0;
                if (lane == 0 && bal) base = (int)atomicAdd(&scnt[1], (unsigned)__popc(bal));
                base = __shfl_sync(0xffffffffu, base, 0);
                if (pr) {
                    int pos = base + __popc(bal & ((1u << lane) - 1u));
                    float wt = __expf(iordf((unsigned)(kv >> 12)) - m);
                    selkw[pos] = ((ull)__float_as_uint(wt) << 32)
                               | (unsigned)(4095 - (int)(kv & 0xFFFull));
                    wsel += wt;
                }
            }
        }
    } else {
        // ---- cold path: massive ties at u == ut ----
        #pragma unroll
        for (int it = 0; it < 4; it++) {
            #pragma unroll
            for (int cc = 0; cc < 4; cc++) {
                unsigned uv = u[it*4 + cc];
                bool pg = (uv > ut), pe = (uv == ut);
                unsigned balg = __ballot_sync(0xffffffffu, pg);
                int baseg = 0;
                if (lane == 0 && balg) baseg = (int)atomicAdd(&scnt[1], (unsigned)__popc(balg));
                baseg = __shfl_sync(0xffffffffu, baseg, 0);
                if (pg) {
                    int pos = baseg + __popc(balg & ((1u << lane) - 1u));
                    float wt = __expf(iordf(uv) - m);
                    selkw[pos] = ((ull)__float_as_uint(wt) << 32)
                               | (unsigned)((tid + it*256)*4 + cc);
                    wsel += wt;
                }
                unsigned bale = __ballot_sync(0xffffffffu, pe);
                int basee = 0;
                if (lane == 0 && bale) basee = (int)atomicAdd(&scnt[2], (unsigned)__popc(bale));
                basee = __shfl_sync(0xffffffffu, basee, 0);
                if (pe) {
                    int pos = basee + __popc(bale & ((1u << lane) - 1u));
                    if (pos < 256) eqidx[pos] = (tid + it*256)*4 + cc;
                }
            }
        }
        __syncthreads();
        if (tid == 0) {
            int ecnt = (int)scnt[2]; if (ecnt > 256) ecnt = 256;
            float wt_eq = __expf(iordf(ut) - m);
            int base = TK_ - need_g;
            for (int a = 0; a < need_g; a++) {
                int bm2 = 0x7FFFFFFF, bi = -1;
                for (int e2 = 0; e2 < ecnt; e2++)
                    if (eqidx[e2] < bm2) { bm2 = eqidx[e2]; bi = e2; }
                eqidx[bi] = 0x7FFFFFFF;
                selkw[base + a] = ((ull)__float_as_uint(wt_eq) << 32) | (unsigned)bm2;
            }
            wsel += (float)need_g * wt_eq;
        }
    }

    // ---- block-reduce the softmax denominator ----
    #pragma unroll
    for (int o = 16; o; o >>= 1) wsel += __shfl_xor_sync(0xffffffffu, wsel, o);
    __syncthreads();                      // selkw complete; warrf reusable
    if (lane == 0) warrf[w] = wsel;
    __syncthreads();
    float wtot = 0.f;
    #pragma unroll
    for (int q = 0; q < 8; q++) wtot += warrf[q];
    float inv = 1.f / wtot;

    // ---- vectorized AV: warp w covers entries w*32..w*32+31 ----
    {
        int g = lane >> 3, sub = lane & 7;
        float4 a4 = make_float4(0.f, 0.f, 0.f, 0.f);
        #pragma unroll
        for (int r = 0; r < 8; r++) {
            int e = w*32 + r*4 + g;
            ull kw = selkw[e];                         // one LDS.64
            int j = (int)(unsigned)(kw & 0xFFFFFFFFull);
            float wt = __uint_as_float((unsigned)(kw >> 32));
            float4 vv = *(const float4*)&vp[(size_t)j*HD_ + sub*4];
            a4.x = fmaf(wt, vv.x, a4.x);
            a4.y = fmaf(wt, vv.y, a4.y);
            a4.z = fmaf(wt, vv.z, a4.z);
            a4.w = fmaf(wt, vv.w, a4.w);
        }
        #pragma unroll
        for (int off = 8; off <= 16; off <<= 1) {
            a4.x += __shfl_xor_sync(0xffffffffu, a4.x, off);
            a4.y += __shfl_xor_sync(0xffffffffu, a4.y, off);
            a4.z += __shfl_xor_sync(0xffffffffu, a4.z, off);
            a4.w += __shfl_xor_sync(0xffffffffu, a4.w, off);
        }
        if (g == 0) ((float4*)racc)[w*8 + sub] = a4;
    }
    __syncthreads();
    if (tid < HD_) {
        float a = 0.f;
        #pragma unroll
        for (int q = 0; q < 8; q++) a += racc[q*HD_ + tid];
        int head = bh & 3, bb = bh >> 2;
        g_att[((size_t)(bb*C_ + head*HD_ + tid)) * N_ + n] = a * inv;
    }
}

// ================= proj + residual (smem-staged W) =================
__global__ void __launch_bounds__(256) proj_kernel(const float* __restrict__ x,
                                                   const float* __restrict__ W,
                                                   const float* __restrict__ bias,
                                                   float* __restrict__ out) {
    __shared__ float as_[C_*64];          // 32 KB
    __shared__ float ws[16*129];          // 8.3 KB  ws[cc*129 + o]
    int n0 = blockIdx.x * 64, bb = blockIdx.y;
    int tid = threadIdx.x;
    const float* ap = g_att + (size_t)bb * C_ * N_;
    for (int i = tid; i < C_*64; i += 256) {
        int c = i >> 6, nl = i & 63;
        as_[i] = ap[(size_t)c*N_ + n0 + nl];
    }

    int nq = tid & 3, og = tid >> 2;
    float acc[2][16];
    #pragma unroll
    for (int k = 0; k < 2; k++)
        #pragma unroll
        for (int j = 0; j < 16; j++) acc[k][j] = 0.f;

    const float4* as4 = (const float4*)as_;
    for (int ch = 0; ch < 8; ch++) {
        int c0 = ch * 16;
        __syncthreads();                       // protect ws from prior compute
        // coalesced load of W[0:128][c0:c0+16] -> transposed ws
        #pragma unroll
        for (int t2 = 0; t2 < 2; t2++) {
            int i = tid + t2*256;              // 0..511 float4s
            int o = i >> 2, h = i & 3;
            float4 wv4 = *(const float4*)&W[(size_t)o*C_ + c0 + h*4];
            int ccb = h * 4;
            ws[(ccb+0)*129 + o] = wv4.x;
            ws[(ccb+1)*129 + o] = wv4.y;
            ws[(ccb+2)*129 + o] = wv4.z;
            ws[(ccb+3)*129 + o] = wv4.w;
        }
        __syncthreads();
        #pragma unroll
        for (int cc = 0; cc < 16; cc++) {
            int c = c0 + cc;
            float4 h0 = as4[c*16 + nq*4 + 0];
            float4 h1 = as4[c*16 + nq*4 + 1];
            float4 h2 = as4[c*16 + nq*4 + 2];
            float4 h3 = as4[c*16 + nq*4 + 3];
            float hv[16] = {h0.x,h0.y,h0.z,h0.w, h1.x,h1.y,h1.z,h1.w,
                            h2.x,h2.y,h2.z,h2.w, h3.x,h3.y,h3.z,h3.w};
            #pragma unroll
            for (int k = 0; k < 2; k++) {
                float wv = ws[cc*129 + og + 64*k];   // broadcast, conflict-free
                #pragma unroll
                for (int j = 0; j < 16; j++) acc[k][j] += wv * hv[j];
            }
        }
    }
    #pragma unroll
    for (int k = 0; k < 2; k++) {
        int o = og + 64*k;
        float bv = bias[o];
        size_t base = ((size_t)bb*C_ + o)*N_ + n0 + nq*16;
        #pragma unroll
        for (int j4 = 0; j4 < 4; j4++) {
            float4 xi = *(const float4*)&x[base + j4*4];
            float4 r;
            r.x = acc[k][j4*4+0] + bv + xi.x;
            r.y = acc[k][j4*4+1] + bv + xi.y;
            r.z = acc[k][j4*4+2] + bv + xi.z;
            r.w = acc[k][j4*4+3] + bv + xi.w;
            *(float4*)&out[base + j4*4] = r;
        }
    }
}

// ================= launch =================
extern "C" void kernel_launch(void* const* d_in, const int* in_sizes, int n_in,
                              void* d_out, int out_size) {
    const float* x      = (const float*)d_in[0];
    const float* gn_w   = (const float*)d_in[1];
    const float* gn_b   = (const float*)d_in[2];
    const float* qkv_w  = (const float*)d_in[3];
    const float* qkv_b  = (const float*)d_in[4];
    const float* proj_w = (const float*)d_in[5];
    const float* proj_b = (const float*)d_in[6];
    float* out = (float*)d_out;

    gn_kernel    <<<B_*GR_, 256>>>(x, gn_w, gn_b);
    qkv_kernel   <<<dim3(N_/64, B_), 256>>>(qkv_w, qkv_b);
    score_kernel <<<dim3(N_/128, N_/128, B_*NH_), 256>>>();
    select_kernel<<<dim3(N_, B_*NH_), 256>>>();
    proj_kernel  <<<dim3(N_/64, B_), 256>>>(x, proj_w, proj_b, out);
}